// round 8
// baseline (speedup 1.0000x reference)
#include <cuda_runtime.h>
#include <cuda_bf16.h>
#include <cstdint>

#define P_N 96
#define S_N 128
#define HN  8
#define HDN 32
#define LN  16
#define EN  256

typedef unsigned long long u64;

__device__ __forceinline__ u64 fma2(u64 a, u64 b, u64 c) {
    u64 d;
    asm("fma.rn.f32x2 %0, %1, %2, %3;" : "=l"(d) : "l"(a), "l"(b), "l"(c));
    return d;
}
__device__ __forceinline__ u64 pack2(float x) {
    u64 d;
    unsigned r = __float_as_uint(x);
    asm("mov.b64 %0, {%1, %1};" : "=l"(d) : "r"(r));
    return d;
}
__device__ __forceinline__ uint32_t smem_u32(const void* p) {
    uint32_t a;
    asm("{ .reg .u64 t; cvta.to.shared.u64 t, %1; cvt.u32.u64 %0, t; }" : "=r"(a) : "l"(p));
    return a;
}

#define LDSM4(r0, r1, r2, r3, addr)                                          \
    asm volatile("ldmatrix.sync.aligned.m8n8.x4.shared.b16 {%0,%1,%2,%3}, [%4];" \
                 : "=r"(r0), "=r"(r1), "=r"(r2), "=r"(r3) : "r"(addr))

#define MMA16816(d, a, b)                                                    \
    asm volatile("mma.sync.aligned.m16n8k16.row.col.f32.bf16.bf16.f32 "      \
                 "{%0,%1,%2,%3}, {%4,%5,%6,%7}, {%8,%9}, {%0,%1,%2,%3};"     \
                 : "+f"((d)[0]), "+f"((d)[1]), "+f"((d)[2]), "+f"((d)[3])    \
                 : "r"((a)[0]), "r"((a)[1]), "r"((a)[2]), "r"((a)[3]),       \
                   "r"((b)[0]), "r"((b)[1]))

// ---------------- scratch (device globals; no allocation allowed) ----------
__device__ uint32_t g_qs[P_N * HN * LN * 32];   // [hi(32bf16)|lo(32bf16)] per (p,h,i)
__device__ uint32_t g_ks[S_N * HN * LN * 32];
__device__ float g_vw[S_N * HN * LN];           // [s][h][j]
__device__ float g_wvf[HN * EN];
__device__ float g_bvf[HN];
__device__ float g_c0;
__device__ float g_part[HN * P_N * S_N];        // per-head partial sums
__device__ int   g_cnt[96];                     // 8 sgroups x 12 pgroups

// ---------------- prep: weff (per-head slice), Wvf, bvf, c0 ----------------
__global__ void __launch_bounds__(256) prep_kernel(
        const float* __restrict__ in_w, const float* __restrict__ in_b,
        const float* __restrict__ Wo,   const float* __restrict__ bo,
        const float* __restrict__ Wop,  const float* __restrict__ bop) {
    const int h = blockIdx.x;
    const int tid = threadIdx.x;
    __shared__ float sweff[HDN];

    {
        int d = tid >> 3, part = tid & 7;
        float a = 0.f;
        int obase = part * 32;
        #pragma unroll 8
        for (int o = 0; o < 32; ++o)
            a = fmaf(Wop[obase + o], Wo[(obase + o) * EN + h * HDN + d], a);
        a += __shfl_xor_sync(0xffffffffu, a, 1);
        a += __shfl_xor_sync(0xffffffffu, a, 2);
        a += __shfl_xor_sync(0xffffffffu, a, 4);
        if (part == 0) sweff[d] = a;
    }
    __syncthreads();
    {
        int e = tid;
        float acc = 0.f;
        #pragma unroll 8
        for (int d = 0; d < HDN; ++d)
            acc = fmaf(in_w[(2 * EN + h * HDN + d) * EN + e], sweff[d], acc);
        g_wvf[h * EN + e] = acc;
    }
    if (tid < 32) {
        float b = in_b[2 * EN + h * HDN + tid] * sweff[tid];
        #pragma unroll
        for (int off = 16; off > 0; off >>= 1)
            b += __shfl_xor_sync(0xffffffffu, b, off);
        if (tid == 0) g_bvf[h] = b;
    }
    if (h == 0) {
        __shared__ float red[EN];
        red[tid] = bo[tid] * Wop[tid];
        __syncthreads();
        for (int s = 128; s > 0; s >>= 1) {
            if (tid < s) red[tid] += red[tid + s];
            __syncthreads();
        }
        if (tid == 0) g_c0 = red[0] + bop[0];
    }
}

// ---------------- Q / K projection + vw (in spare z=0 blocks) --------------
__global__ void __launch_bounds__(256) proj_kernel(const float* __restrict__ pano,
                                                   const float* __restrict__ sat,
                                                   const float* __restrict__ in_w,
                                                   const float* __restrict__ in_b) {
    const int z = blockIdx.z;
    const float* X;
    int rtiles, woff;
    if (z == 0) { X = pano; rtiles = 24; woff = 0;  }
    else        { X = sat;  rtiles = 32; woff = EN; }

    if (z == 0 && blockIdx.x >= 24) {
        // ---- vw[s,h,j] = sat[s,j,:] . Wvf[h,:] + bvf[h] (32 spare blocks) ----
        int sid = (blockIdx.x - 24) * 4 + blockIdx.y;   // 0..31
        int T = sid * 256 + threadIdx.x;                // 0..8191
        int h = T & 7, r0 = T >> 3;                     // r0 in [0,1024)
        float bv = g_bvf[h];
        const float4* __restrict__ w = (const float4*)(g_wvf + h * EN);
        #pragma unroll
        for (int it = 0; it < 2; ++it) {
            int r = r0 + it * 1024;
            const float4* __restrict__ x = (const float4*)(sat + r * EN);
            float acc = bv;
            #pragma unroll 16
            for (int e4 = 0; e4 < 64; ++e4) {
                float4 a = x[e4], b = w[e4];
                acc = fmaf(a.x, b.x, acc);
                acc = fmaf(a.y, b.y, acc);
                acc = fmaf(a.z, b.z, acc);
                acc = fmaf(a.w, b.w, acc);
            }
            g_vw[(r >> 4) * (HN * LN) + h * LN + (r & 15)] = acc;
        }
        return;
    }

    const int m0 = blockIdx.x * 64;
    const int n0 = blockIdx.y * 64;

    __shared__ __align__(16) float As[32][68];
    __shared__ __align__(16) float Ws[32][68];

    const int tid = threadIdx.x;
    const int tx = tid & 15, ty = tid >> 4;

    u64 acc2[4][2];
    #pragma unroll
    for (int i = 0; i < 4; ++i) { acc2[i][0] = 0ull; acc2[i][1] = 0ull; }

    for (int k0 = 0; k0 < EN; k0 += 32) {
        #pragma unroll
        for (int t = 0; t < 8; ++t) {
            int idx = tid + t * 256;
            int m = idx >> 5, kk = idx & 31;
            As[kk][m] = X[(m0 + m) * EN + k0 + kk];
            Ws[kk][m] = in_w[(woff + n0 + m) * EN + k0 + kk];
        }
        __syncthreads();
        #pragma unroll
        for (int kk = 0; kk < 32; ++kk) {
            float4 a = *(const float4*)&As[kk][ty * 4];
            ulonglong2 b2 = *(const ulonglong2*)&Ws[kk][tx * 4];
            const float av[4] = {a.x, a.y, a.z, a.w};
            #pragma unroll
            for (int i = 0; i < 4; ++i) {
                u64 aq = pack2(av[i]);
                acc2[i][0] = fma2(aq, b2.x, acc2[i][0]);
                acc2[i][1] = fma2(aq, b2.y, acc2[i][1]);
            }
        }
        __syncthreads();
    }

    #pragma unroll
    for (int i = 0; i < 4; ++i) {
        int row = m0 + ty * 4 + i;              // x*16 + (i|j)
        int xr = row >> 4, ri = row & 15;
        #pragma unroll
        for (int jp = 0; jp < 2; ++jp) {
            float2 v2 = *(float2*)&acc2[i][jp];
            int col0 = n0 + tx * 4 + jp * 2;
            int h = col0 >> 5, d = col0 & 31;
            float va = v2.x + in_b[woff + col0];
            float vb = v2.y + in_b[woff + col0 + 1];
            if (z == 0) { va *= 0.17677669529663687f; vb *= 0.17677669529663687f; }
            __nv_bfloat16 ha = __float2bfloat16(va);
            __nv_bfloat16 hb = __float2bfloat16(vb);
            __nv_bfloat16 la = __float2bfloat16(va - __bfloat162float(ha));
            __nv_bfloat16 lb = __float2bfloat16(vb - __bfloat162float(hb));
            uint32_t hw = ((uint32_t)__bfloat16_as_ushort(hb) << 16) | __bfloat16_as_ushort(ha);
            uint32_t lw = ((uint32_t)__bfloat16_as_ushort(lb) << 16) | __bfloat16_as_ushort(la);
            int base = ((xr * HN + h) * LN + ri) * 32 + (d >> 1);
            if (z == 0) { g_qs[base] = hw; g_qs[base + 16] = lw; }
            else        { g_ks[base] = hw; g_ks[base + 16] = lw; }
        }
    }
}

// ---------------- HMMA attention + in-kernel final reduce ------------------
// grid = (8 s-groups, 12 p-octets, 8 heads). 128 threads = 4 warps.
#define ROWB   144
#define QBASE  0
#define KBASE  18432                 // 128 rows * 144
#define VWBASE 55296                 // KBASE + 256*144
#define ASMEM_BYTES 56320            // VWBASE + 1024

__global__ void __launch_bounds__(128) attn_mma_kernel(float* __restrict__ out) {
    extern __shared__ __align__(16) char smx[];
    const uint32_t sb = smem_u32(smx);
    const int tid = threadIdx.x;
    const int warp = tid >> 5, lane = tid & 31;
    const int t = lane & 3;
    const int h = blockIdx.z;
    const int p0 = blockIdx.y * 8;
    const int s0 = blockIdx.x * 16;

    // ---- stage Q: 8 panos x 16 i rows ----
    {
        const uint4* __restrict__ src = (const uint4*)g_qs;
        #pragma unroll
        for (int tt = 0; tt < 8; ++tt) {
            int u = tid + tt * 128;            // 0..1023 = row*8 + chunk
            int row = u >> 3, ch = u & 7;
            int pp = row >> 4, ii = row & 15;
            uint4 v = src[(((p0 + pp) * HN + h) * LN + ii) * 8 + ch];
            *(uint4*)(smx + QBASE + row * ROWB + ch * 16) = v;
        }
    }
    // ---- stage K: 16 sats x 16 j rows ----
    {
        const uint4* __restrict__ src = (const uint4*)g_ks;
        #pragma unroll
        for (int tt = 0; tt < 16; ++tt) {
            int u = tid + tt * 128;            // 0..2047
            int row = u >> 3, ch = u & 7;
            int sp = row >> 4, jj = row & 15;
            uint4 v = src[(((s0 + sp) * HN + h) * LN + jj) * 8 + ch];
            *(uint4*)(smx + KBASE + row * ROWB + ch * 16) = v;
        }
    }
    // ---- stage vw [16 s'][16 j] ----
    {
        #pragma unroll
        for (int tt = 0; tt < 2; ++tt) {
            int u = tid + tt * 128;            // 0..255
            *(float*)(smx + VWBASE + u * 4) =
                g_vw[(s0 + (u >> 4)) * (HN * LN) + h * LN + (u & 15)];
        }
    }
    __syncthreads();

    const float* vws = (const float*)(smx + VWBASE);

    // ---- hoist ALL B fragments (iter-invariant): 4 npair x 2 nn x 4 kb x 2 ----
    uint32_t Bf[4][2][4][2];
    #pragma unroll
    for (int npair = 0; npair < 4; ++npair)
        #pragma unroll
        for (int nn = 0; nn < 2; ++nn) {
            int N0 = warp * 64 + (npair * 2 + nn) * 8;
            uint32_t rowaddr = sb + KBASE + (N0 + (lane & 7)) * ROWB + ((lane >> 3) * 16);
            LDSM4(Bf[npair][nn][0][0], Bf[npair][nn][0][1],
                  Bf[npair][nn][1][0], Bf[npair][nn][1][1], rowaddr);
            LDSM4(Bf[npair][nn][2][0], Bf[npair][nn][2][1],
                  Bf[npair][nn][3][0], Bf[npair][nn][3][1], rowaddr + 64);
        }

    for (int iter = 0; iter < 4; ++iter) {
        uint32_t A[2][4][4];
        #pragma unroll
        for (int m = 0; m < 2; ++m) {
            int R0 = iter * 32 + m * 16;
            uint32_t rowaddr = sb + QBASE + (R0 + (lane & 15)) * ROWB + ((lane >> 4) * 16);
            #pragma unroll
            for (int kb = 0; kb < 4; ++kb)
                LDSM4(A[m][kb][0], A[m][kb][1], A[m][kb][2], A[m][kb][3],
                      rowaddr + kb * 32);
        }

        #pragma unroll
        for (int npair = 0; npair < 4; ++npair) {
            float acc[2][2][4];
            #pragma unroll
            for (int m = 0; m < 2; ++m)
                #pragma unroll
                for (int nn = 0; nn < 2; ++nn)
                    #pragma unroll
                    for (int c = 0; c < 4; ++c) acc[m][nn][c] = 0.f;

            #pragma unroll
            for (int m = 0; m < 2; ++m)
                #pragma unroll
                for (int nn = 0; nn < 2; ++nn) {
                    MMA16816(acc[m][nn], A[m][0], Bf[npair][nn][0]);  // qh.kh d0-15
                    MMA16816(acc[m][nn], A[m][1], Bf[npair][nn][1]);  // qh.kh d16-31
                    MMA16816(acc[m][nn], A[m][0], Bf[npair][nn][2]);  // qh.kl
                    MMA16816(acc[m][nn], A[m][1], Bf[npair][nn][3]);
                    MMA16816(acc[m][nn], A[m][2], Bf[npair][nn][0]);  // ql.kh
                    MMA16816(acc[m][nn], A[m][3], Bf[npair][nn][1]);
                }

            int sl = warp * 4 + npair;                 // local sat
            float vw0 = vws[sl * 16 + 2 * t];
            float vw1 = vws[sl * 16 + 2 * t + 1];
            float vw2 = vws[sl * 16 + 2 * t + 8];
            float vw3 = vws[sl * 16 + 2 * t + 9];

            #pragma unroll
            for (int m = 0; m < 2; ++m) {
                float e0 = __expf(acc[m][0][0]);
                float e1 = __expf(acc[m][0][1]);
                float e2 = __expf(acc[m][1][0]);
                float e3 = __expf(acc[m][1][1]);
                float num = e0 * vw0 + e1 * vw1 + e2 * vw2 + e3 * vw3;
                float den = e0 + e1 + e2 + e3;
                float f0 = __expf(acc[m][0][2]);
                float f1 = __expf(acc[m][0][3]);
                float f2 = __expf(acc[m][1][2]);
                float f3 = __expf(acc[m][1][3]);
                float numh = f0 * vw0 + f1 * vw1 + f2 * vw2 + f3 * vw3;
                float denh = f0 + f1 + f2 + f3;

                num  += __shfl_xor_sync(0xffffffffu, num, 1);
                den  += __shfl_xor_sync(0xffffffffu, den, 1);
                numh += __shfl_xor_sync(0xffffffffu, numh, 1);
                denh += __shfl_xor_sync(0xffffffffu, denh, 1);
                num  += __shfl_xor_sync(0xffffffffu, num, 2);
                den  += __shfl_xor_sync(0xffffffffu, den, 2);
                numh += __shfl_xor_sync(0xffffffffu, numh, 2);
                denh += __shfl_xor_sync(0xffffffffu, denh, 2);

                float val = __fdividef(num, den) + __fdividef(numh, denh);
                val += __shfl_xor_sync(0xffffffffu, val, 4);
                val += __shfl_xor_sync(0xffffffffu, val, 8);
                val += __shfl_xor_sync(0xffffffffu, val, 16);

                if (lane == 0)
                    g_part[(h * P_N + p0 + iter * 2 + m) * S_N + s0 + sl] = val;
            }
        }
    }

    // ---- last block per (sgroup,pgroup) tile sums the 8 heads -> out ----
    __shared__ int s_last;
    __threadfence();
    __syncthreads();
    if (tid == 0) {
        int old = atomicAdd(&g_cnt[blockIdx.x * 12 + blockIdx.y], 1);
        s_last = (old == 7);
    }
    __syncthreads();
    if (s_last) {
        __threadfence();
        int pp = tid >> 4, sl = tid & 15;        // 8 x 16 = 128 outputs
        float acc = 0.f;
        #pragma unroll
        for (int hh = 0; hh < HN; ++hh)
            acc += g_part[(hh * P_N + p0 + pp) * S_N + s0 + sl];
        out[(p0 + pp) * S_N + s0 + sl] = acc * (1.f / 16.f) + g_c0;
        if (tid == 0) g_cnt[blockIdx.x * 12 + blockIdx.y] = 0;   // reset for next replay
    }
}

// ---------------- launch ---------------------------------------------------
extern "C" void kernel_launch(void* const* d_in, const int* in_sizes, int n_in,
                              void* d_out, int out_size) {
    const float* sat   = (const float*)d_in[0];
    const float* pano  = (const float*)d_in[1];
    const float* in_w  = (const float*)d_in[2];
    const float* in_b  = (const float*)d_in[3];
    const float* out_w = (const float*)d_in[4];
    const float* out_b = (const float*)d_in[5];
    const float* op_w  = (const float*)d_in[6];
    const float* op_b  = (const float*)d_in[7];
    float* out = (float*)d_out;

    cudaFuncSetAttribute(attn_mma_kernel, cudaFuncAttributeMaxDynamicSharedMemorySize,
                         ASMEM_BYTES);

    prep_kernel<<<8, 256>>>(in_w, in_b, out_w, out_b, op_w, op_b);
    proj_kernel<<<dim3(32, 4, 2), 256>>>(pano, sat, in_w, in_b);
    attn_mma_kernel<<<dim3(8, 12, 8), 128, ASMEM_BYTES>>>(out);
}

// round 9
// speedup vs baseline: 1.0088x; 1.0088x over previous
#include <cuda_runtime.h>
#include <cuda_bf16.h>
#include <cstdint>

#define P_N 96
#define S_N 128
#define HN  8
#define HDN 32
#define LN  16
#define EN  256

typedef unsigned long long u64;

__device__ __forceinline__ u64 fma2(u64 a, u64 b, u64 c) {
    u64 d;
    asm("fma.rn.f32x2 %0, %1, %2, %3;" : "=l"(d) : "l"(a), "l"(b), "l"(c));
    return d;
}
__device__ __forceinline__ u64 pack2(float x) {
    u64 d;
    unsigned r = __float_as_uint(x);
    asm("mov.b64 %0, {%1, %1};" : "=l"(d) : "r"(r));
    return d;
}
__device__ __forceinline__ uint32_t smem_u32(const void* p) {
    uint32_t a;
    asm("{ .reg .u64 t; cvta.to.shared.u64 t, %1; cvt.u32.u64 %0, t; }" : "=r"(a) : "l"(p));
    return a;
}

#define LDSM4(r0, r1, r2, r3, addr)                                          \
    asm volatile("ldmatrix.sync.aligned.m8n8.x4.shared.b16 {%0,%1,%2,%3}, [%4];" \
                 : "=r"(r0), "=r"(r1), "=r"(r2), "=r"(r3) : "r"(addr))

#define MMA16816(d, a, b)                                                    \
    asm volatile("mma.sync.aligned.m16n8k16.row.col.f32.bf16.bf16.f32 "      \
                 "{%0,%1,%2,%3}, {%4,%5,%6,%7}, {%8,%9}, {%0,%1,%2,%3};"     \
                 : "+f"((d)[0]), "+f"((d)[1]), "+f"((d)[2]), "+f"((d)[3])    \
                 : "r"((a)[0]), "r"((a)[1]), "r"((a)[2]), "r"((a)[3]),       \
                   "r"((b)[0]), "r"((b)[1]))

// ---------------- scratch (device globals; no allocation allowed) ----------
__device__ uint32_t g_qs[P_N * HN * LN * 32];   // [hi(32bf16)|lo(32bf16)] per (p,h,i)
__device__ uint32_t g_ks[S_N * HN * LN * 32];
__device__ float g_vw[S_N * HN * LN];           // [s][h][j]
__device__ float g_weff[EN];
__device__ float g_wvf[HN * EN];
__device__ float g_bvf[HN];
__device__ float g_c0;
__device__ float g_part[HN * P_N * S_N];        // per-head partial sums
__device__ int   g_cnt[96];                     // 8 sgroups x 12 pgroups

// ---------------- prep 1: weff[e] = sum_o Wop[o]*Wo[o][e];  c0 -------------
// grid = 16 blocks x 256 threads. Block eb: e in [eb*16, eb*16+16).
// Thread (opart = tid>>4, e_off = tid&15): opart covers 16 o's; coalesced in e.
__global__ void __launch_bounds__(256) prep_weff_kernel(
        const float* __restrict__ Wo, const float* __restrict__ bo,
        const float* __restrict__ Wop, const float* __restrict__ bop) {
    const int tid = threadIdx.x;
    const int e = blockIdx.x * 16 + (tid & 15);
    const int opart = tid >> 4;
    __shared__ float part[16][17];

    float a = 0.f;
    #pragma unroll
    for (int o = 0; o < 16; ++o)
        a = fmaf(Wop[opart * 16 + o], Wo[(opart * 16 + o) * EN + e], a);
    part[opart][tid & 15] = a;
    __syncthreads();
    if (tid < 16) {
        float s = 0.f;
        #pragma unroll
        for (int op = 0; op < 16; ++op) s += part[op][tid];
        g_weff[blockIdx.x * 16 + tid] = s;
    }
    if (blockIdx.x == 0) {
        __shared__ float red[EN];
        red[tid] = bo[tid] * Wop[tid];
        __syncthreads();
        for (int s = 128; s > 0; s >>= 1) {
            if (tid < s) red[tid] += red[tid + s];
            __syncthreads();
        }
        if (tid == 0) g_c0 = red[0] + bop[0];
    }
}

// ---------------- prep 2: Wvf[h][e], bvf[h] --------------------------------
// grid = 8 blocks (h), 256 threads (e). Coalesced in e, unrolled in d.
__global__ void __launch_bounds__(256) prep_wvf_kernel(
        const float* __restrict__ in_w, const float* __restrict__ in_b) {
    const int h = blockIdx.x;
    const int tid = threadIdx.x;
    __shared__ float sweff[HDN];
    if (tid < 32) sweff[tid] = g_weff[h * HDN + tid];
    __syncthreads();

    float acc = 0.f;
    #pragma unroll 8
    for (int d = 0; d < HDN; ++d)
        acc = fmaf(in_w[(2 * EN + h * HDN + d) * EN + tid], sweff[d], acc);
    g_wvf[h * EN + tid] = acc;

    if (tid < 32) {
        float b = in_b[2 * EN + h * HDN + tid] * sweff[tid];
        #pragma unroll
        for (int off = 16; off > 0; off >>= 1)
            b += __shfl_xor_sync(0xffffffffu, b, off);
        if (tid == 0) g_bvf[h] = b;
    }
}

// ---------------- Q / K projection + vw (in spare z=0 blocks) --------------
__global__ void __launch_bounds__(256) proj_kernel(const float* __restrict__ pano,
                                                   const float* __restrict__ sat,
                                                   const float* __restrict__ in_w,
                                                   const float* __restrict__ in_b) {
    const int z = blockIdx.z;
    const float* X;
    int woff;
    if (z == 0) { X = pano; woff = 0;  }
    else        { X = sat;  woff = EN; }

    if (z == 0 && blockIdx.x >= 24) {
        // ---- vw[s,h,j] = sat[s,j,:] . Wvf[h,:] + bvf[h] (32 spare blocks) ----
        int sid = (blockIdx.x - 24) * 4 + blockIdx.y;   // 0..31
        int T = sid * 256 + threadIdx.x;                // 0..8191
        int h = T & 7, r0 = T >> 3;                     // r0 in [0,1024)
        float bv = g_bvf[h];
        const float4* __restrict__ w = (const float4*)(g_wvf + h * EN);
        #pragma unroll
        for (int it = 0; it < 2; ++it) {
            int r = r0 + it * 1024;
            const float4* __restrict__ x = (const float4*)(sat + r * EN);
            float acc = bv;
            #pragma unroll 16
            for (int e4 = 0; e4 < 64; ++e4) {
                float4 a = x[e4], b = w[e4];
                acc = fmaf(a.x, b.x, acc);
                acc = fmaf(a.y, b.y, acc);
                acc = fmaf(a.z, b.z, acc);
                acc = fmaf(a.w, b.w, acc);
            }
            g_vw[(r >> 4) * (HN * LN) + h * LN + (r & 15)] = acc;
        }
        return;
    }

    const int m0 = blockIdx.x * 64;
    const int n0 = blockIdx.y * 64;

    __shared__ __align__(16) float As[32][68];
    __shared__ __align__(16) float Ws[32][68];

    const int tid = threadIdx.x;
    const int tx = tid & 15, ty = tid >> 4;

    u64 acc2[4][2];
    #pragma unroll
    for (int i = 0; i < 4; ++i) { acc2[i][0] = 0ull; acc2[i][1] = 0ull; }

    // register prefetch buffers (double buffering)
    float xr[8], wr[8];
    #pragma unroll
    for (int t = 0; t < 8; ++t) {
        int idx = tid + t * 256;
        int m = idx >> 5, kk = idx & 31;
        xr[t] = X[(m0 + m) * EN + kk];
        wr[t] = in_w[(woff + n0 + m) * EN + kk];
    }

    for (int c = 0; c < 8; ++c) {
        #pragma unroll
        for (int t = 0; t < 8; ++t) {
            int idx = tid + t * 256;
            int m = idx >> 5, kk = idx & 31;
            As[kk][m] = xr[t];
            Ws[kk][m] = wr[t];
        }
        __syncthreads();
        if (c < 7) {
            int k0 = (c + 1) * 32;
            #pragma unroll
            for (int t = 0; t < 8; ++t) {
                int idx = tid + t * 256;
                int m = idx >> 5, kk = idx & 31;
                xr[t] = X[(m0 + m) * EN + k0 + kk];
                wr[t] = in_w[(woff + n0 + m) * EN + k0 + kk];
            }
        }
        #pragma unroll
        for (int kk = 0; kk < 32; ++kk) {
            float4 a = *(const float4*)&As[kk][ty * 4];
            ulonglong2 b2 = *(const ulonglong2*)&Ws[kk][tx * 4];
            const float av[4] = {a.x, a.y, a.z, a.w};
            #pragma unroll
            for (int i = 0; i < 4; ++i) {
                u64 aq = pack2(av[i]);
                acc2[i][0] = fma2(aq, b2.x, acc2[i][0]);
                acc2[i][1] = fma2(aq, b2.y, acc2[i][1]);
            }
        }
        __syncthreads();
    }

    #pragma unroll
    for (int i = 0; i < 4; ++i) {
        int row = m0 + ty * 4 + i;              // x*16 + (i|j)
        int xr2 = row >> 4, ri = row & 15;
        #pragma unroll
        for (int jp = 0; jp < 2; ++jp) {
            float2 v2 = *(float2*)&acc2[i][jp];
            int col0 = n0 + tx * 4 + jp * 2;
            int h = col0 >> 5, d = col0 & 31;
            float va = v2.x + in_b[woff + col0];
            float vb = v2.y + in_b[woff + col0 + 1];
            if (z == 0) { va *= 0.17677669529663687f; vb *= 0.17677669529663687f; }
            __nv_bfloat16 ha = __float2bfloat16(va);
            __nv_bfloat16 hb = __float2bfloat16(vb);
            __nv_bfloat16 la = __float2bfloat16(va - __bfloat162float(ha));
            __nv_bfloat16 lb = __float2bfloat16(vb - __bfloat162float(hb));
            uint32_t hw = ((uint32_t)__bfloat16_as_ushort(hb) << 16) | __bfloat16_as_ushort(ha);
            uint32_t lw = ((uint32_t)__bfloat16_as_ushort(lb) << 16) | __bfloat16_as_ushort(la);
            int base = ((xr2 * HN + h) * LN + ri) * 32 + (d >> 1);
            if (z == 0) { g_qs[base] = hw; g_qs[base + 16] = lw; }
            else        { g_ks[base] = hw; g_ks[base + 16] = lw; }
        }
    }
}

// ---------------- HMMA attention + in-kernel final reduce ------------------
// grid = (8 s-groups, 12 p-octets, 8 heads). 128 threads = 4 warps.
#define ROWB   144
#define QBASE  0
#define KBASE  18432                 // 128 rows * 144
#define VWBASE 55296                 // KBASE + 256*144
#define ASMEM_BYTES 56320            // VWBASE + 1024

__global__ void __launch_bounds__(128) attn_mma_kernel(float* __restrict__ out) {
    extern __shared__ __align__(16) char smx[];
    const uint32_t sb = smem_u32(smx);
    const int tid = threadIdx.x;
    const int warp = tid >> 5, lane = tid & 31;
    const int t = lane & 3;
    const int h = blockIdx.z;
    const int p0 = blockIdx.y * 8;
    const int s0 = blockIdx.x * 16;

    // ---- stage Q: 8 panos x 16 i rows ----
    {
        const uint4* __restrict__ src = (const uint4*)g_qs;
        #pragma unroll
        for (int tt = 0; tt < 8; ++tt) {
            int u = tid + tt * 128;            // 0..1023 = row*8 + chunk
            int row = u >> 3, ch = u & 7;
            int pp = row >> 4, ii = row & 15;
            uint4 v = src[(((p0 + pp) * HN + h) * LN + ii) * 8 + ch];
            *(uint4*)(smx + QBASE + row * ROWB + ch * 16) = v;
        }
    }
    // ---- stage K: 16 sats x 16 j rows ----
    {
        const uint4* __restrict__ src = (const uint4*)g_ks;
        #pragma unroll
        for (int tt = 0; tt < 16; ++tt) {
            int u = tid + tt * 128;            // 0..2047
            int row = u >> 3, ch = u & 7;
            int sp = row >> 4, jj = row & 15;
            uint4 v = src[(((s0 + sp) * HN + h) * LN + jj) * 8 + ch];
            *(uint4*)(smx + KBASE + row * ROWB + ch * 16) = v;
        }
    }
    // ---- stage vw [16 s'][16 j] ----
    {
        #pragma unroll
        for (int tt = 0; tt < 2; ++tt) {
            int u = tid + tt * 128;            // 0..255
            *(float*)(smx + VWBASE + u * 4) =
                g_vw[(s0 + (u >> 4)) * (HN * LN) + h * LN + (u & 15)];
        }
    }
    __syncthreads();

    const float* vws = (const float*)(smx + VWBASE);

    // ---- hoist ALL B fragments (iter-invariant) ----
    uint32_t Bf[4][2][4][2];
    #pragma unroll
    for (int npair = 0; npair < 4; ++npair)
        #pragma unroll
        for (int nn = 0; nn < 2; ++nn) {
            int N0 = warp * 64 + (npair * 2 + nn) * 8;
            uint32_t rowaddr = sb + KBASE + (N0 + (lane & 7)) * ROWB + ((lane >> 3) * 16);
            LDSM4(Bf[npair][nn][0][0], Bf[npair][nn][0][1],
                  Bf[npair][nn][1][0], Bf[npair][nn][1][1], rowaddr);
            LDSM4(Bf[npair][nn][2][0], Bf[npair][nn][2][1],
                  Bf[npair][nn][3][0], Bf[npair][nn][3][1], rowaddr + 64);
        }

    for (int iter = 0; iter < 4; ++iter) {
        uint32_t A[2][4][4];
        #pragma unroll
        for (int m = 0; m < 2; ++m) {
            int R0 = iter * 32 + m * 16;
            uint32_t rowaddr = sb + QBASE + (R0 + (lane & 15)) * ROWB + ((lane >> 4) * 16);
            #pragma unroll
            for (int kb = 0; kb < 4; ++kb)
                LDSM4(A[m][kb][0], A[m][kb][1], A[m][kb][2], A[m][kb][3],
                      rowaddr + kb * 32);
        }

        #pragma unroll
        for (int npair = 0; npair < 4; ++npair) {
            float acc[2][2][4];
            #pragma unroll
            for (int m = 0; m < 2; ++m)
                #pragma unroll
                for (int nn = 0; nn < 2; ++nn)
                    #pragma unroll
                    for (int c = 0; c < 4; ++c) acc[m][nn][c] = 0.f;

            #pragma unroll
            for (int m = 0; m < 2; ++m)
                #pragma unroll
                for (int nn = 0; nn < 2; ++nn) {
                    MMA16816(acc[m][nn], A[m][0], Bf[npair][nn][0]);  // qh.kh d0-15
                    MMA16816(acc[m][nn], A[m][1], Bf[npair][nn][1]);  // qh.kh d16-31
                    MMA16816(acc[m][nn], A[m][0], Bf[npair][nn][2]);  // qh.kl
                    MMA16816(acc[m][nn], A[m][1], Bf[npair][nn][3]);
                    MMA16816(acc[m][nn], A[m][2], Bf[npair][nn][0]);  // ql.kh
                    MMA16816(acc[m][nn], A[m][3], Bf[npair][nn][1]);
                }

            int sl = warp * 4 + npair;                 // local sat
            float vw0 = vws[sl * 16 + 2 * t];
            float vw1 = vws[sl * 16 + 2 * t + 1];
            float vw2 = vws[sl * 16 + 2 * t + 8];
            float vw3 = vws[sl * 16 + 2 * t + 9];

            #pragma unroll
            for (int m = 0; m < 2; ++m) {
                float e0 = __expf(acc[m][0][0]);
                float e1 = __expf(acc[m][0][1]);
                float e2 = __expf(acc[m][1][0]);
                float e3 = __expf(acc[m][1][1]);
                float num = e0 * vw0 + e1 * vw1 + e2 * vw2 + e3 * vw3;
                float den = e0 + e1 + e2 + e3;
                float f0 = __expf(acc[m][0][2]);
                float f1 = __expf(acc[m][0][3]);
                float f2 = __expf(acc[m][1][2]);
                float f3 = __expf(acc[m][1][3]);
                float numh = f0 * vw0 + f1 * vw1 + f2 * vw2 + f3 * vw3;
                float denh = f0 + f1 + f2 + f3;

                num  += __shfl_xor_sync(0xffffffffu, num, 1);
                den  += __shfl_xor_sync(0xffffffffu, den, 1);
                numh += __shfl_xor_sync(0xffffffffu, numh, 1);
                denh += __shfl_xor_sync(0xffffffffu, denh, 1);
                num  += __shfl_xor_sync(0xffffffffu, num, 2);
                den  += __shfl_xor_sync(0xffffffffu, den, 2);
                numh += __shfl_xor_sync(0xffffffffu, numh, 2);
                denh += __shfl_xor_sync(0xffffffffu, denh, 2);

                float val = __fdividef(num, den) + __fdividef(numh, denh);
                val += __shfl_xor_sync(0xffffffffu, val, 4);
                val += __shfl_xor_sync(0xffffffffu, val, 8);
                val += __shfl_xor_sync(0xffffffffu, val, 16);

                if (lane == 0)
                    g_part[(h * P_N + p0 + iter * 2 + m) * S_N + s0 + sl] = val;
            }
        }
    }

    // ---- last block per (sgroup,pgroup) tile sums the 8 heads -> out ----
    __shared__ int s_last;
    __threadfence();
    __syncthreads();
    if (tid == 0) {
        int old = atomicAdd(&g_cnt[blockIdx.x * 12 + blockIdx.y], 1);
        s_last = (old == 7);
    }
    __syncthreads();
    if (s_last) {
        __threadfence();
        int pp = tid >> 4, sl = tid & 15;        // 8 x 16 = 128 outputs
        float acc = 0.f;
        #pragma unroll
        for (int hh = 0; hh < HN; ++hh)
            acc += g_part[(hh * P_N + p0 + pp) * S_N + s0 + sl];
        out[(p0 + pp) * S_N + s0 + sl] = acc * (1.f / 16.f) + g_c0;
        if (tid == 0) g_cnt[blockIdx.x * 12 + blockIdx.y] = 0;   // reset for next replay
    }
}

// ---------------- launch ---------------------------------------------------
extern "C" void kernel_launch(void* const* d_in, const int* in_sizes, int n_in,
                              void* d_out, int out_size) {
    const float* sat   = (const float*)d_in[0];
    const float* pano  = (const float*)d_in[1];
    const float* in_w  = (const float*)d_in[2];
    const float* in_b  = (const float*)d_in[3];
    const float* out_w = (const float*)d_in[4];
    const float* out_b = (const float*)d_in[5];
    const float* op_w  = (const float*)d_in[6];
    const float* op_b  = (const float*)d_in[7];
    float* out = (float*)d_out;

    cudaFuncSetAttribute(attn_mma_kernel, cudaFuncAttributeMaxDynamicSharedMemorySize,
                         ASMEM_BYTES);

    prep_weff_kernel<<<16, 256>>>(out_w, out_b, op_w, op_b);
    prep_wvf_kernel<<<8, 256>>>(in_w, in_b);
    proj_kernel<<<dim3(32, 4, 2), 256>>>(pano, sat, in_w, in_b);
    attn_mma_kernel<<<dim3(8, 12, 8), 128, ASMEM_BYTES>>>(out);
}

// round 10
// speedup vs baseline: 1.0325x; 1.0235x over previous
#include <cuda_runtime.h>
#include <cuda_bf16.h>
#include <cstdint>

#define P_N 96
#define S_N 128
#define HN  8
#define HDN 32
#define LN  16
#define EN  256

typedef unsigned long long u64;

__device__ __forceinline__ u64 fma2(u64 a, u64 b, u64 c) {
    u64 d;
    asm("fma.rn.f32x2 %0, %1, %2, %3;" : "=l"(d) : "l"(a), "l"(b), "l"(c));
    return d;
}
__device__ __forceinline__ u64 pack2(float x) {
    u64 d;
    unsigned r = __float_as_uint(x);
    asm("mov.b64 %0, {%1, %1};" : "=l"(d) : "r"(r));
    return d;
}
__device__ __forceinline__ uint32_t smem_u32(const void* p) {
    uint32_t a;
    asm("{ .reg .u64 t; cvta.to.shared.u64 t, %1; cvt.u32.u64 %0, t; }" : "=r"(a) : "l"(p));
    return a;
}

#define LDSM4(r0, r1, r2, r3, addr)                                          \
    asm volatile("ldmatrix.sync.aligned.m8n8.x4.shared.b16 {%0,%1,%2,%3}, [%4];" \
                 : "=r"(r0), "=r"(r1), "=r"(r2), "=r"(r3) : "r"(addr))

#define MMA16816(d, a, b)                                                    \
    asm volatile("mma.sync.aligned.m16n8k16.row.col.f32.bf16.bf16.f32 "      \
                 "{%0,%1,%2,%3}, {%4,%5,%6,%7}, {%8,%9}, {%0,%1,%2,%3};"     \
                 : "+f"((d)[0]), "+f"((d)[1]), "+f"((d)[2]), "+f"((d)[3])    \
                 : "r"((a)[0]), "r"((a)[1]), "r"((a)[2]), "r"((a)[3]),       \
                   "r"((b)[0]), "r"((b)[1]))

// ---------------- scratch (device globals; no allocation allowed) ----------
__device__ uint32_t g_qs[P_N * HN * LN * 32];   // [hi(32bf16)|lo(32bf16)] per (p,h,i)
__device__ uint32_t g_ks[S_N * HN * LN * 32];
__device__ float g_vw[S_N * HN * LN];           // [s][h][j]
__device__ float g_wvf[HN * EN];
__device__ float g_bvf[HN];
__device__ float g_c0;
__device__ float g_part[HN * P_N * S_N];        // per-head partial sums
__device__ int   g_cnt[192];                    // 16 sgroups x 12 pgroups

// ---------------- prep (merged): per-head weff slice, Wvf, bvf, c0 ---------
// grid = 8 blocks (h), 256 threads.
__global__ void __launch_bounds__(256) prep_kernel(
        const float* __restrict__ in_w, const float* __restrict__ in_b,
        const float* __restrict__ Wo,   const float* __restrict__ bo,
        const float* __restrict__ Wop,  const float* __restrict__ bop) {
    const int h = blockIdx.x;
    const int tid = threadIdx.x;
    __shared__ float part[8][33];
    __shared__ float sweff[HDN];

    // weff[h*32+d] = sum_o Wop[o]*Wo[o][h*32+d]; coalesced in d, o split x8.
    {
        int d = tid & 31, opart = tid >> 5;
        float a = 0.f;
        #pragma unroll 8
        for (int o = 0; o < 32; ++o)
            a = fmaf(Wop[opart * 32 + o], Wo[(opart * 32 + o) * EN + h * HDN + d], a);
        part[opart][d] = a;
    }
    __syncthreads();
    if (tid < 32) {
        float s = 0.f;
        #pragma unroll
        for (int op = 0; op < 8; ++op) s += part[op][tid];
        sweff[tid] = s;
    }
    __syncthreads();

    // Wvf[h][e]
    {
        float acc = 0.f;
        #pragma unroll 8
        for (int d = 0; d < HDN; ++d)
            acc = fmaf(in_w[(2 * EN + h * HDN + d) * EN + tid], sweff[d], acc);
        g_wvf[h * EN + tid] = acc;
    }
    // bvf[h]
    if (tid < 32) {
        float b = in_b[2 * EN + h * HDN + tid] * sweff[tid];
        #pragma unroll
        for (int off = 16; off > 0; off >>= 1)
            b += __shfl_xor_sync(0xffffffffu, b, off);
        if (tid == 0) g_bvf[h] = b;
    }
    // c0 (block 0)
    if (h == 0) {
        __shared__ float red[EN];
        red[tid] = bo[tid] * Wop[tid];
        __syncthreads();
        for (int s = 128; s > 0; s >>= 1) {
            if (tid < s) red[tid] += red[tid + s];
            __syncthreads();
        }
        if (tid == 0) g_c0 = red[0] + bop[0];
    }
}

// ---------------- Q / K projection + vw (in spare z=0 blocks) --------------
__global__ void __launch_bounds__(256) proj_kernel(const float* __restrict__ pano,
                                                   const float* __restrict__ sat,
                                                   const float* __restrict__ in_w,
                                                   const float* __restrict__ in_b) {
    const int z = blockIdx.z;
    const float* X;
    int woff;
    if (z == 0) { X = pano; woff = 0;  }
    else        { X = sat;  woff = EN; }

    if (z == 0 && blockIdx.x >= 24) {
        // ---- vw[s,h,j] = sat[s,j,:] . Wvf[h,:] + bvf[h] (32 spare blocks) ----
        int sid = (blockIdx.x - 24) * 4 + blockIdx.y;   // 0..31
        int T = sid * 256 + threadIdx.x;                // 0..8191
        int h = T & 7, r0 = T >> 3;                     // r0 in [0,1024)
        float bv = g_bvf[h];
        const float4* __restrict__ w = (const float4*)(g_wvf + h * EN);
        #pragma unroll
        for (int it = 0; it < 2; ++it) {
            int r = r0 + it * 1024;
            const float4* __restrict__ x = (const float4*)(sat + r * EN);
            float acc = bv;
            #pragma unroll 16
            for (int e4 = 0; e4 < 64; ++e4) {
                float4 a = x[e4], b = w[e4];
                acc = fmaf(a.x, b.x, acc);
                acc = fmaf(a.y, b.y, acc);
                acc = fmaf(a.z, b.z, acc);
                acc = fmaf(a.w, b.w, acc);
            }
            g_vw[(r >> 4) * (HN * LN) + h * LN + (r & 15)] = acc;
        }
        return;
    }

    const int m0 = blockIdx.x * 64;
    const int n0 = blockIdx.y * 64;

    __shared__ __align__(16) float As[32][68];
    __shared__ __align__(16) float Ws[32][68];

    const int tid = threadIdx.x;
    const int tx = tid & 15, ty = tid >> 4;

    u64 acc2[4][2];
    #pragma unroll
    for (int i = 0; i < 4; ++i) { acc2[i][0] = 0ull; acc2[i][1] = 0ull; }

    float xr[8], wr[8];
    #pragma unroll
    for (int t = 0; t < 8; ++t) {
        int idx = tid + t * 256;
        int m = idx >> 5, kk = idx & 31;
        xr[t] = X[(m0 + m) * EN + kk];
        wr[t] = in_w[(woff + n0 + m) * EN + kk];
    }

    for (int c = 0; c < 8; ++c) {
        #pragma unroll
        for (int t = 0; t < 8; ++t) {
            int idx = tid + t * 256;
            int m = idx >> 5, kk = idx & 31;
            As[kk][m] = xr[t];
            Ws[kk][m] = wr[t];
        }
        __syncthreads();
        if (c < 7) {
            int k0 = (c + 1) * 32;
            #pragma unroll
            for (int t = 0; t < 8; ++t) {
                int idx = tid + t * 256;
                int m = idx >> 5, kk = idx & 31;
                xr[t] = X[(m0 + m) * EN + k0 + kk];
                wr[t] = in_w[(woff + n0 + m) * EN + k0 + kk];
            }
        }
        #pragma unroll
        for (int kk = 0; kk < 32; ++kk) {
            float4 a = *(const float4*)&As[kk][ty * 4];
            ulonglong2 b2 = *(const ulonglong2*)&Ws[kk][tx * 4];
            const float av[4] = {a.x, a.y, a.z, a.w};
            #pragma unroll
            for (int i = 0; i < 4; ++i) {
                u64 aq = pack2(av[i]);
                acc2[i][0] = fma2(aq, b2.x, acc2[i][0]);
                acc2[i][1] = fma2(aq, b2.y, acc2[i][1]);
            }
        }
        __syncthreads();
    }

    #pragma unroll
    for (int i = 0; i < 4; ++i) {
        int row = m0 + ty * 4 + i;              // x*16 + (i|j)
        int xr2 = row >> 4, ri = row & 15;
        #pragma unroll
        for (int jp = 0; jp < 2; ++jp) {
            float2 v2 = *(float2*)&acc2[i][jp];
            int col0 = n0 + tx * 4 + jp * 2;
            int h = col0 >> 5, d = col0 & 31;
            float va = v2.x + in_b[woff + col0];
            float vb = v2.y + in_b[woff + col0 + 1];
            if (z == 0) { va *= 0.17677669529663687f; vb *= 0.17677669529663687f; }
            __nv_bfloat16 ha = __float2bfloat16(va);
            __nv_bfloat16 hb = __float2bfloat16(vb);
            __nv_bfloat16 la = __float2bfloat16(va - __bfloat162float(ha));
            __nv_bfloat16 lb = __float2bfloat16(vb - __bfloat162float(hb));
            uint32_t hw = ((uint32_t)__bfloat16_as_ushort(hb) << 16) | __bfloat16_as_ushort(ha);
            uint32_t lw = ((uint32_t)__bfloat16_as_ushort(lb) << 16) | __bfloat16_as_ushort(la);
            int base = ((xr2 * HN + h) * LN + ri) * 32 + (d >> 1);
            if (z == 0) { g_qs[base] = hw; g_qs[base + 16] = lw; }
            else        { g_ks[base] = hw; g_ks[base + 16] = lw; }
        }
    }
}

// ---------------- HMMA attention + in-kernel final reduce ------------------
// grid = (16 s-groups, 12 p-octets, 8 heads). 128 threads = 4 warps.
// Block tile: 8 panos x 8 sats x 1 head. Warp: 2 sats.
#define ROWB   144
#define QBASE  0
#define KBASE  18432                 // 128 rows * 144
#define VWBASE 36864                 // KBASE + 128*144
#define ASMEM_BYTES 37376            // VWBASE + 512

__global__ void __launch_bounds__(128) attn_mma_kernel(float* __restrict__ out) {
    extern __shared__ __align__(16) char smx[];
    const uint32_t sb = smem_u32(smx);
    const int tid = threadIdx.x;
    const int warp = tid >> 5, lane = tid & 31;
    const int t = lane & 3;
    const int h = blockIdx.z;
    const int p0 = blockIdx.y * 8;
    const int s0 = blockIdx.x * 8;

    // ---- stage Q: 8 panos x 16 i rows ----
    {
        const uint4* __restrict__ src = (const uint4*)g_qs;
        #pragma unroll
        for (int tt = 0; tt < 8; ++tt) {
            int u = tid + tt * 128;            // 0..1023 = row*8 + chunk
            int row = u >> 3, ch = u & 7;
            int pp = row >> 4, ii = row & 15;
            uint4 v = src[(((p0 + pp) * HN + h) * LN + ii) * 8 + ch];
            *(uint4*)(smx + QBASE + row * ROWB + ch * 16) = v;
        }
    }
    // ---- stage K: 8 sats x 16 j rows ----
    {
        const uint4* __restrict__ src = (const uint4*)g_ks;
        #pragma unroll
        for (int tt = 0; tt < 8; ++tt) {
            int u = tid + tt * 128;            // 0..1023
            int row = u >> 3, ch = u & 7;
            int sp = row >> 4, jj = row & 15;
            uint4 v = src[(((s0 + sp) * HN + h) * LN + jj) * 8 + ch];
            *(uint4*)(smx + KBASE + row * ROWB + ch * 16) = v;
        }
    }
    // ---- stage vw [8 s'][16 j] ----
    if (tid < 128) {
        *(float*)(smx + VWBASE + tid * 4) =
            g_vw[(s0 + (tid >> 4)) * (HN * LN) + h * LN + (tid & 15)];
    }
    __syncthreads();

    const float* vws = (const float*)(smx + VWBASE);

    for (int iter = 0; iter < 4; ++iter) {
        uint32_t A[2][4][4];
        #pragma unroll
        for (int m = 0; m < 2; ++m) {
            int R0 = iter * 32 + m * 16;
            uint32_t rowaddr = sb + QBASE + (R0 + (lane & 15)) * ROWB + ((lane >> 4) * 16);
            #pragma unroll
            for (int kb = 0; kb < 4; ++kb)
                LDSM4(A[m][kb][0], A[m][kb][1], A[m][kb][2], A[m][kb][3],
                      rowaddr + kb * 32);
        }

        #pragma unroll
        for (int npair = 0; npair < 2; ++npair) {
            uint32_t Bf[2][4][2];
            #pragma unroll
            for (int nn = 0; nn < 2; ++nn) {
                int N0 = warp * 32 + (npair * 2 + nn) * 8;
                uint32_t rowaddr = sb + KBASE + (N0 + (lane & 7)) * ROWB + ((lane >> 3) * 16);
                LDSM4(Bf[nn][0][0], Bf[nn][0][1], Bf[nn][1][0], Bf[nn][1][1], rowaddr);
                LDSM4(Bf[nn][2][0], Bf[nn][2][1], Bf[nn][3][0], Bf[nn][3][1], rowaddr + 64);
            }

            float acc[2][2][4];
            #pragma unroll
            for (int m = 0; m < 2; ++m)
                #pragma unroll
                for (int nn = 0; nn < 2; ++nn)
                    #pragma unroll
                    for (int c = 0; c < 4; ++c) acc[m][nn][c] = 0.f;

            #pragma unroll
            for (int m = 0; m < 2; ++m)
                #pragma unroll
                for (int nn = 0; nn < 2; ++nn) {
                    MMA16816(acc[m][nn], A[m][0], Bf[nn][0]);  // qh.kh d0-15
                    MMA16816(acc[m][nn], A[m][1], Bf[nn][1]);  // qh.kh d16-31
                    MMA16816(acc[m][nn], A[m][0], Bf[nn][2]);  // qh.kl
                    MMA16816(acc[m][nn], A[m][1], Bf[nn][3]);
                    MMA16816(acc[m][nn], A[m][2], Bf[nn][0]);  // ql.kh
                    MMA16816(acc[m][nn], A[m][3], Bf[nn][1]);
                }

            int sl = warp * 2 + npair;                 // local sat 0..7
            float vw0 = vws[sl * 16 + 2 * t];
            float vw1 = vws[sl * 16 + 2 * t + 1];
            float vw2 = vws[sl * 16 + 2 * t + 8];
            float vw3 = vws[sl * 16 + 2 * t + 9];

            #pragma unroll
            for (int m = 0; m < 2; ++m) {
                float e0 = __expf(acc[m][0][0]);
                float e1 = __expf(acc[m][0][1]);
                float e2 = __expf(acc[m][1][0]);
                float e3 = __expf(acc[m][1][1]);
                float num = e0 * vw0 + e1 * vw1 + e2 * vw2 + e3 * vw3;
                float den = e0 + e1 + e2 + e3;
                float f0 = __expf(acc[m][0][2]);
                float f1 = __expf(acc[m][0][3]);
                float f2 = __expf(acc[m][1][2]);
                float f3 = __expf(acc[m][1][3]);
                float numh = f0 * vw0 + f1 * vw1 + f2 * vw2 + f3 * vw3;
                float denh = f0 + f1 + f2 + f3;

                num  += __shfl_xor_sync(0xffffffffu, num, 1);
                den  += __shfl_xor_sync(0xffffffffu, den, 1);
                numh += __shfl_xor_sync(0xffffffffu, numh, 1);
                denh += __shfl_xor_sync(0xffffffffu, denh, 1);
                num  += __shfl_xor_sync(0xffffffffu, num, 2);
                den  += __shfl_xor_sync(0xffffffffu, den, 2);
                numh += __shfl_xor_sync(0xffffffffu, numh, 2);
                denh += __shfl_xor_sync(0xffffffffu, denh, 2);

                float val = __fdividef(num, den) + __fdividef(numh, denh);
                val += __shfl_xor_sync(0xffffffffu, val, 4);
                val += __shfl_xor_sync(0xffffffffu, val, 8);
                val += __shfl_xor_sync(0xffffffffu, val, 16);

                if (lane == 0)
                    g_part[(h * P_N + p0 + iter * 2 + m) * S_N + s0 + sl] = val;
            }
        }
    }

    // ---- last block per (sgroup,pgroup) tile sums the 8 heads -> out ----
    __shared__ int s_last;
    __threadfence();
    __syncthreads();
    if (tid == 0) {
        int old = atomicAdd(&g_cnt[blockIdx.x * 12 + blockIdx.y], 1);
        s_last = (old == 7);
    }
    __syncthreads();
    if (s_last) {
        __threadfence();
        if (tid < 64) {
            int pp = tid >> 3, sl = tid & 7;     // 8 x 8 = 64 outputs
            float acc = 0.f;
            #pragma unroll
            for (int hh = 0; hh < HN; ++hh)
                acc += g_part[(hh * P_N + p0 + pp) * S_N + s0 + sl];
            out[(p0 + pp) * S_N + s0 + sl] = acc * (1.f / 16.f) + g_c0;
        }
        if (tid == 0) g_cnt[blockIdx.x * 12 + blockIdx.y] = 0;   // reset for next replay
    }
}

// ---------------- launch ---------------------------------------------------
extern "C" void kernel_launch(void* const* d_in, const int* in_sizes, int n_in,
                              void* d_out, int out_size) {
    const float* sat   = (const float*)d_in[0];
    const float* pano  = (const float*)d_in[1];
    const float* in_w  = (const float*)d_in[2];
    const float* in_b  = (const float*)d_in[3];
    const float* out_w = (const float*)d_in[4];
    const float* out_b = (const float*)d_in[5];
    const float* op_w  = (const float*)d_in[6];
    const float* op_b  = (const float*)d_in[7];
    float* out = (float*)d_out;

    cudaFuncSetAttribute(attn_mma_kernel, cudaFuncAttributeMaxDynamicSharedMemorySize,
                         ASMEM_BYTES);

    prep_kernel<<<8, 256>>>(in_w, in_b, out_w, out_b, op_w, op_b);
    proj_kernel<<<dim3(32, 4, 2), 256>>>(pano, sat, in_w, in_b);
    attn_mma_kernel<<<dim3(16, 12, 8), 128, ASMEM_BYTES>>>(out);
}

// round 11
// speedup vs baseline: 1.2919x; 1.2513x over previous
#include <cuda_runtime.h>
#include <cuda_bf16.h>
#include <cstdint>

#define P_N 96
#define S_N 128
#define HN  8
#define HDN 32
#define LN  16
#define EN  256

typedef unsigned long long u64;

__device__ __forceinline__ u64 fma2(u64 a, u64 b, u64 c) {
    u64 d;
    asm("fma.rn.f32x2 %0, %1, %2, %3;" : "=l"(d) : "l"(a), "l"(b), "l"(c));
    return d;
}
__device__ __forceinline__ u64 pack2(float x) {
    u64 d;
    unsigned r = __float_as_uint(x);
    asm("mov.b64 %0, {%1, %1};" : "=l"(d) : "r"(r));
    return d;
}
__device__ __forceinline__ uint32_t smem_u32(const void* p) {
    uint32_t a;
    asm("{ .reg .u64 t; cvta.to.shared.u64 t, %1; cvt.u32.u64 %0, t; }" : "=r"(a) : "l"(p));
    return a;
}

#define LDSM4(r0, r1, r2, r3, addr)                                          \
    asm volatile("ldmatrix.sync.aligned.m8n8.x4.shared.b16 {%0,%1,%2,%3}, [%4];" \
                 : "=r"(r0), "=r"(r1), "=r"(r2), "=r"(r3) : "r"(addr))

#define MMA16816(d, a, b)                                                    \
    asm volatile("mma.sync.aligned.m16n8k16.row.col.f32.bf16.bf16.f32 "      \
                 "{%0,%1,%2,%3}, {%4,%5,%6,%7}, {%8,%9}, {%0,%1,%2,%3};"     \
                 : "+f"((d)[0]), "+f"((d)[1]), "+f"((d)[2]), "+f"((d)[3])    \
                 : "r"((a)[0]), "r"((a)[1]), "r"((a)[2]), "r"((a)[3]),       \
                   "r"((b)[0]), "r"((b)[1]))

// ---------------- scratch (device globals; no allocation allowed) ----------
__device__ uint32_t g_qs[P_N * HN * LN * 32];   // [hi(32bf16)|lo(32bf16)] per (p,h,i)
__device__ uint32_t g_ks[S_N * HN * LN * 32];
__device__ float g_vw[S_N * HN * LN];           // [s][h][j]
__device__ float g_c0;
__device__ float g_part[HN * P_N * S_N];        // per-head partial sums
__device__ int   g_cnt[192];                    // 16 sgroups x 12 pgroups

// ---------------- Q / K projection + fused prep+vw (spare z=0 blocks) ------
__global__ void __launch_bounds__(256) proj_kernel(
        const float* __restrict__ pano, const float* __restrict__ sat,
        const float* __restrict__ in_w, const float* __restrict__ in_b,
        const float* __restrict__ Wo,   const float* __restrict__ bo,
        const float* __restrict__ Wop,  const float* __restrict__ bop) {
    const int z = blockIdx.z;
    const float* X;
    int woff;
    if (z == 0) { X = pano; woff = 0;  }
    else        { X = sat;  woff = EN; }

    if (z == 0 && blockIdx.x >= 24) {
        // ==== spare blocks: self-contained prep (weff -> Wvf, bvf, c0) + vw ====
        const int sid = (blockIdx.x - 24) * 4 + blockIdx.y;   // 0..31
        const int tid = threadIdx.x;
        __shared__ float sweff[EN];
        __shared__ float swvf[HN * 260];       // padded: h*260 -> conflict-free
        __shared__ float sbvf[HN];

        // weff[e] = sum_o Wop[o] * Wo[o][e]   (coalesced in e)
        {
            float acc = 0.f;
            #pragma unroll 16
            for (int o = 0; o < EN; ++o)
                acc = fmaf(Wop[o], Wo[o * EN + tid], acc);
            sweff[tid] = acc;
        }
        __syncthreads();
        // Wvf[h][e] = sum_d Wv[h*32+d][e] * weff[h*32+d]
        #pragma unroll
        for (int h = 0; h < HN; ++h) {
            float acc = 0.f;
            #pragma unroll 8
            for (int d = 0; d < HDN; ++d)
                acc = fmaf(in_w[(2 * EN + h * HDN + d) * EN + tid], sweff[h * HDN + d], acc);
            swvf[h * 260 + tid] = acc;
        }
        if (tid < 8) {
            float b = 0.f;
            #pragma unroll
            for (int d = 0; d < HDN; ++d)
                b = fmaf(in_b[2 * EN + tid * HDN + d], sweff[tid * HDN + d], b);
            sbvf[tid] = b;
        }
        if (sid == 0) {
            __shared__ float red[EN];
            red[tid] = bo[tid] * Wop[tid];
            __syncthreads();
            for (int s = 128; s > 0; s >>= 1) {
                if (tid < s) red[tid] += red[tid + s];
                __syncthreads();
            }
            if (tid == 0) g_c0 = red[0] + bop[0];
        }
        __syncthreads();

        // vw[s,h,j] = sat[s,j,:] . Wvf[h,:] + bvf[h]   (64 rows per block)
        const int T = sid * 256 + tid;         // 0..8191
        const int h = T & 7, r0 = T >> 3;      // r0 in [0,1024)
        const float bv = sbvf[h];
        const float* w = swvf + h * 260;
        #pragma unroll
        for (int it = 0; it < 2; ++it) {
            int r = r0 + it * 1024;
            const float4* __restrict__ x = (const float4*)(sat + r * EN);
            float acc = bv;
            #pragma unroll 16
            for (int e4 = 0; e4 < 64; ++e4) {
                float4 a = x[e4];
                float4 b = *(const float4*)(w + e4 * 4);
                acc = fmaf(a.x, b.x, acc);
                acc = fmaf(a.y, b.y, acc);
                acc = fmaf(a.z, b.z, acc);
                acc = fmaf(a.w, b.w, acc);
            }
            g_vw[(r >> 4) * (HN * LN) + h * LN + (r & 15)] = acc;
        }
        return;
    }

    const int m0 = blockIdx.x * 64;
    const int n0 = blockIdx.y * 64;

    __shared__ __align__(16) float As[32][68];
    __shared__ __align__(16) float Ws[32][68];

    const int tid = threadIdx.x;
    const int tx = tid & 15, ty = tid >> 4;

    u64 acc2[4][2];
    #pragma unroll
    for (int i = 0; i < 4; ++i) { acc2[i][0] = 0ull; acc2[i][1] = 0ull; }

    float xr[8], wr[8];
    #pragma unroll
    for (int t = 0; t < 8; ++t) {
        int idx = tid + t * 256;
        int m = idx >> 5, kk = idx & 31;
        xr[t] = X[(m0 + m) * EN + kk];
        wr[t] = in_w[(woff + n0 + m) * EN + kk];
    }

    for (int c = 0; c < 8; ++c) {
        #pragma unroll
        for (int t = 0; t < 8; ++t) {
            int idx = tid + t * 256;
            int m = idx >> 5, kk = idx & 31;
            As[kk][m] = xr[t];
            Ws[kk][m] = wr[t];
        }
        __syncthreads();
        if (c < 7) {
            int k0 = (c + 1) * 32;
            #pragma unroll
            for (int t = 0; t < 8; ++t) {
                int idx = tid + t * 256;
                int m = idx >> 5, kk = idx & 31;
                xr[t] = X[(m0 + m) * EN + k0 + kk];
                wr[t] = in_w[(woff + n0 + m) * EN + k0 + kk];
            }
        }
        #pragma unroll
        for (int kk = 0; kk < 32; ++kk) {
            float4 a = *(const float4*)&As[kk][ty * 4];
            ulonglong2 b2 = *(const ulonglong2*)&Ws[kk][tx * 4];
            const float av[4] = {a.x, a.y, a.z, a.w};
            #pragma unroll
            for (int i = 0; i < 4; ++i) {
                u64 aq = pack2(av[i]);
                acc2[i][0] = fma2(aq, b2.x, acc2[i][0]);
                acc2[i][1] = fma2(aq, b2.y, acc2[i][1]);
            }
        }
        __syncthreads();
    }

    #pragma unroll
    for (int i = 0; i < 4; ++i) {
        int row = m0 + ty * 4 + i;              // x*16 + (i|j)
        int xr2 = row >> 4, ri = row & 15;
        #pragma unroll
        for (int jp = 0; jp < 2; ++jp) {
            float2 v2 = *(float2*)&acc2[i][jp];
            int col0 = n0 + tx * 4 + jp * 2;
            int h = col0 >> 5, d = col0 & 31;
            float va = v2.x + in_b[woff + col0];
            float vb = v2.y + in_b[woff + col0 + 1];
            if (z == 0) { va *= 0.17677669529663687f; vb *= 0.17677669529663687f; }
            __nv_bfloat16 ha = __float2bfloat16(va);
            __nv_bfloat16 hb = __float2bfloat16(vb);
            __nv_bfloat16 la = __float2bfloat16(va - __bfloat162float(ha));
            __nv_bfloat16 lb = __float2bfloat16(vb - __bfloat162float(hb));
            uint32_t hw = ((uint32_t)__bfloat16_as_ushort(hb) << 16) | __bfloat16_as_ushort(ha);
            uint32_t lw = ((uint32_t)__bfloat16_as_ushort(lb) << 16) | __bfloat16_as_ushort(la);
            int base = ((xr2 * HN + h) * LN + ri) * 32 + (d >> 1);
            if (z == 0) { g_qs[base] = hw; g_qs[base + 16] = lw; }
            else        { g_ks[base] = hw; g_ks[base + 16] = lw; }
        }
    }
}

// ---------------- HMMA attention + in-kernel final reduce ------------------
// grid = (16 s-groups, 12 p-octets, 8 heads). 128 threads = 4 warps.
#define ROWB   144
#define QBASE  0
#define KBASE  18432                 // 128 rows * 144
#define VWBASE 36864                 // KBASE + 128*144
#define ASMEM_BYTES 37376            // VWBASE + 512

__global__ void __launch_bounds__(128) attn_mma_kernel(float* __restrict__ out) {
    extern __shared__ __align__(16) char smx[];
    const uint32_t sb = smem_u32(smx);
    const int tid = threadIdx.x;
    const int warp = tid >> 5, lane = tid & 31;
    const int t = lane & 3;
    const int h = blockIdx.z;
    const int p0 = blockIdx.y * 8;
    const int s0 = blockIdx.x * 8;

    // ---- stage Q: 8 panos x 16 i rows ----
    {
        const uint4* __restrict__ src = (const uint4*)g_qs;
        #pragma unroll
        for (int tt = 0; tt < 8; ++tt) {
            int u = tid + tt * 128;            // 0..1023 = row*8 + chunk
            int row = u >> 3, ch = u & 7;
            int pp = row >> 4, ii = row & 15;
            uint4 v = src[(((p0 + pp) * HN + h) * LN + ii) * 8 + ch];
            *(uint4*)(smx + QBASE + row * ROWB + ch * 16) = v;
        }
    }
    // ---- stage K: 8 sats x 16 j rows ----
    {
        const uint4* __restrict__ src = (const uint4*)g_ks;
        #pragma unroll
        for (int tt = 0; tt < 8; ++tt) {
            int u = tid + tt * 128;            // 0..1023
            int row = u >> 3, ch = u & 7;
            int sp = row >> 4, jj = row & 15;
            uint4 v = src[(((s0 + sp) * HN + h) * LN + jj) * 8 + ch];
            *(uint4*)(smx + KBASE + row * ROWB + ch * 16) = v;
        }
    }
    // ---- stage vw [8 s'][16 j] ----
    if (tid < 128) {
        *(float*)(smx + VWBASE + tid * 4) =
            g_vw[(s0 + (tid >> 4)) * (HN * LN) + h * LN + (tid & 15)];
    }
    __syncthreads();

    const float* vws = (const float*)(smx + VWBASE);

    for (int iter = 0; iter < 4; ++iter) {
        uint32_t A[2][4][4];
        #pragma unroll
        for (int m = 0; m < 2; ++m) {
            int R0 = iter * 32 + m * 16;
            uint32_t rowaddr = sb + QBASE + (R0 + (lane & 15)) * ROWB + ((lane >> 4) * 16);
            #pragma unroll
            for (int kb = 0; kb < 4; ++kb)
                LDSM4(A[m][kb][0], A[m][kb][1], A[m][kb][2], A[m][kb][3],
                      rowaddr + kb * 32);
        }

        #pragma unroll
        for (int npair = 0; npair < 2; ++npair) {
            uint32_t Bf[2][4][2];
            #pragma unroll
            for (int nn = 0; nn < 2; ++nn) {
                int N0 = warp * 32 + (npair * 2 + nn) * 8;
                uint32_t rowaddr = sb + KBASE + (N0 + (lane & 7)) * ROWB + ((lane >> 3) * 16);
                LDSM4(Bf[nn][0][0], Bf[nn][0][1], Bf[nn][1][0], Bf[nn][1][1], rowaddr);
                LDSM4(Bf[nn][2][0], Bf[nn][2][1], Bf[nn][3][0], Bf[nn][3][1], rowaddr + 64);
            }

            float acc[2][2][4];
            #pragma unroll
            for (int m = 0; m < 2; ++m)
                #pragma unroll
                for (int nn = 0; nn < 2; ++nn)
                    #pragma unroll
                    for (int c = 0; c < 4; ++c) acc[m][nn][c] = 0.f;

            #pragma unroll
            for (int m = 0; m < 2; ++m)
                #pragma unroll
                for (int nn = 0; nn < 2; ++nn) {
                    MMA16816(acc[m][nn], A[m][0], Bf[nn][0]);  // qh.kh d0-15
                    MMA16816(acc[m][nn], A[m][1], Bf[nn][1]);  // qh.kh d16-31
                    MMA16816(acc[m][nn], A[m][0], Bf[nn][2]);  // qh.kl
                    MMA16816(acc[m][nn], A[m][1], Bf[nn][3]);
                    MMA16816(acc[m][nn], A[m][2], Bf[nn][0]);  // ql.kh
                    MMA16816(acc[m][nn], A[m][3], Bf[nn][1]);
                }

            int sl = warp * 2 + npair;                 // local sat 0..7
            float vw0 = vws[sl * 16 + 2 * t];
            float vw1 = vws[sl * 16 + 2 * t + 1];
            float vw2 = vws[sl * 16 + 2 * t + 8];
            float vw3 = vws[sl * 16 + 2 * t + 9];

            #pragma unroll
            for (int m = 0; m < 2; ++m) {
                float e0 = __expf(acc[m][0][0]);
                float e1 = __expf(acc[m][0][1]);
                float e2 = __expf(acc[m][1][0]);
                float e3 = __expf(acc[m][1][1]);
                float num = e0 * vw0 + e1 * vw1 + e2 * vw2 + e3 * vw3;
                float den = e0 + e1 + e2 + e3;
                float f0 = __expf(acc[m][0][2]);
                float f1 = __expf(acc[m][0][3]);
                float f2 = __expf(acc[m][1][2]);
                float f3 = __expf(acc[m][1][3]);
                float numh = f0 * vw0 + f1 * vw1 + f2 * vw2 + f3 * vw3;
                float denh = f0 + f1 + f2 + f3;

                num  += __shfl_xor_sync(0xffffffffu, num, 1);
                den  += __shfl_xor_sync(0xffffffffu, den, 1);
                numh += __shfl_xor_sync(0xffffffffu, numh, 1);
                denh += __shfl_xor_sync(0xffffffffu, denh, 1);
                num  += __shfl_xor_sync(0xffffffffu, num, 2);
                den  += __shfl_xor_sync(0xffffffffu, den, 2);
                numh += __shfl_xor_sync(0xffffffffu, numh, 2);
                denh += __shfl_xor_sync(0xffffffffu, denh, 2);

                float val = __fdividef(num, den) + __fdividef(numh, denh);
                val += __shfl_xor_sync(0xffffffffu, val, 4);
                val += __shfl_xor_sync(0xffffffffu, val, 8);
                val += __shfl_xor_sync(0xffffffffu, val, 16);

                if (lane == 0)
                    g_part[(h * P_N + p0 + iter * 2 + m) * S_N + s0 + sl] = val;
            }
        }
    }

    // ---- last block per (sgroup,pgroup) tile sums the 8 heads -> out ----
    __shared__ int s_last;
    __threadfence();
    __syncthreads();
    if (tid == 0) {
        int old = atomicAdd(&g_cnt[blockIdx.x * 12 + blockIdx.y], 1);
        s_last = (old == 7);
    }
    __syncthreads();
    if (s_last) {
        __threadfence();
        if (tid < 64) {
            int pp = tid >> 3, sl = tid & 7;     // 8 x 8 = 64 outputs
            float acc = 0.f;
            #pragma unroll
            for (int hh = 0; hh < HN; ++hh)
                acc += g_part[(hh * P_N + p0 + pp) * S_N + s0 + sl];
            out[(p0 + pp) * S_N + s0 + sl] = acc * (1.f / 16.f) + g_c0;
        }
        if (tid == 0) g_cnt[blockIdx.x * 12 + blockIdx.y] = 0;   // reset for next replay
    }
}

// ---------------- launch ---------------------------------------------------
extern "C" void kernel_launch(void* const* d_in, const int* in_sizes, int n_in,
                              void* d_out, int out_size) {
    const float* sat   = (const float*)d_in[0];
    const float* pano  = (const float*)d_in[1];
    const float* in_w  = (const float*)d_in[2];
    const float* in_b  = (const float*)d_in[3];
    const float* out_w = (const float*)d_in[4];
    const float* out_b = (const float*)d_in[5];
    const float* op_w  = (const float*)d_in[6];
    const float* op_b  = (const float*)d_in[7];
    float* out = (float*)d_out;

    cudaFuncSetAttribute(attn_mma_kernel, cudaFuncAttributeMaxDynamicSharedMemorySize,
                         ASMEM_BYTES);

    proj_kernel<<<dim3(32, 4, 2), 256>>>(pano, sat, in_w, in_b,
                                         out_w, out_b, op_w, op_b);
    attn_mma_kernel<<<dim3(16, 12, 8), 128, ASMEM_BYTES>>>(out);
}